// round 16
// baseline (speedup 1.0000x reference)
#include <cuda_runtime.h>
#include <cuda_bf16.h>
#include <cstdint>

// Problem constants
#define NUM_CHIPS 4
#define SEQ 1024
#define HIDDEN 2048
#define TOP_K 4
#define N_EXPERTS 32
#define MAX_TOK 1024
#define META_LEN 8
#define N_PER_CHIP (SEQ * TOP_K)           // 4096
#define N_TOTAL (NUM_CHIPS * N_PER_CHIP)   // 16384 assignments
#define N_CHUNKS (N_TOTAL / 32)            // 512 warp-chunks, chip-major
#define TOTAL_SLOTS (N_EXPERTS * MAX_TOK)  // 32768
#define BUF_ELEMS ((size_t)TOTAL_SLOTS * HIDDEN)
#define META_OFF  BUF_ELEMS
#define CNT_OFF   (BUF_ELEMS + (size_t)TOTAL_SLOTS * META_LEN)

#define PLANNERS 64            // planner blocks (wave-1 resident, never wait on slot blocks)
#define THREADS 256
#define NSYNC 1024             // spread sync lines
#define PBARS_PER_REPLAY 3     // planner barriers per replay (epoch = ticket / (3*PLANNERS))

// Scratch (no allocations allowed). ALL counters MONOTONE across graph replays.
__device__ int g_src[TOTAL_SLOTS];            // slot -> assignment id
__device__ int g_cnt[N_EXPERTS];              // per-expert totals
__device__ int g_wcount[N_EXPERTS][N_CHUNKS]; // chunk counts -> (in place) offsets
__device__ unsigned g_pbar;                   // planner barrier tickets (+192/replay)
__device__ unsigned g_tick[NSYNC][32];        // slot tickets: row k&1023, +32/replay
__device__ unsigned g_flag[NSYNC][32];        // done flags: row value == replays completed

// Monotone-window barrier among the PLANNERS planner blocks.
__device__ __forceinline__ unsigned pbar() {
    __shared__ unsigned s_t;
    __syncthreads();
    __threadfence();
    if (threadIdx.x == 0) {
        const unsigned t = atomicAdd(&g_pbar, 1u);
        s_t = t;
        const unsigned tgt = (t / PLANNERS + 1u) * PLANNERS;
        while (*(volatile unsigned*)&g_pbar < tgt) { }
    }
    __syncthreads();
    __threadfence();
    return s_t;
}

__global__ void __launch_bounds__(THREADS) dispatch_kernel(
    const float* __restrict__ x, const float* __restrict__ w,
    const int* __restrict__ idx, float* __restrict__ out)
{
    const int b = blockIdx.x;

    // ---------------- Planner blocks (bid 0..63) ---------------------------
    if (b < PLANNERS) {
        const int warp = threadIdx.x >> 5;            // 0..7
        const int lane = threadIdx.x & 31;
        const unsigned lt = (1u << lane) - 1u;
        const int chunk = b * 8 + warp;               // 0..511, chip-major
        const int a = chunk * 32 + lane;              // assignment id

        // Phase 1: stable rank within chunk + per-chunk expert counts.
        const int e = __ldg(&idx[a]);
        const unsigned m = __match_any_sync(0xFFFFFFFFu, e);
        const int rk = __popc(m & lt);
        g_wcount[lane][chunk] = 0;                    // zero this chunk's column
        __syncwarp();
        if (rk == 0) g_wcount[e][chunk] = __popc(m);  // group leader

        const unsigned t1 = pbar();
        const unsigned epoch = t1 / (PBARS_PER_REPLAY * PLANNERS);  // replay index

        // Phase 2: block 0 scans each expert's 512 chunk counts in place.
        // 8 warps x 4 experts; lane owns 16 contiguous chunks (two-level scan).
        if (b == 0) {
#pragma unroll
            for (int k = 0; k < 4; k++) {
                const int ex = warp * 4 + k;
                const int4* wc = reinterpret_cast<const int4*>(&g_wcount[ex][lane * 16]);
                int4 c0 = wc[0], c1 = wc[1], c2 = wc[2], c3 = wc[3];
                int cnt[16] = {c0.x,c0.y,c0.z,c0.w, c1.x,c1.y,c1.z,c1.w,
                               c2.x,c2.y,c2.z,c2.w, c3.x,c3.y,c3.z,c3.w};
                int lsum = 0;
#pragma unroll
                for (int j = 0; j < 16; j++) lsum += cnt[j];
                int s = lsum;
#pragma unroll
                for (int d = 1; d < 32; d <<= 1) {
                    int t = __shfl_up_sync(0xFFFFFFFFu, s, d);
                    if (lane >= d) s += t;
                }
                int run = s - lsum;
                const int total = __shfl_sync(0xFFFFFFFFu, s, 31);
                int ov[16];
#pragma unroll
                for (int j = 0; j < 16; j++) { ov[j] = run; run += cnt[j]; }
                int4* wo = reinterpret_cast<int4*>(&g_wcount[ex][lane * 16]);
                wo[0] = make_int4(ov[0],  ov[1],  ov[2],  ov[3]);
                wo[1] = make_int4(ov[4],  ov[5],  ov[6],  ov[7]);
                wo[2] = make_int4(ov[8],  ov[9],  ov[10], ov[11]);
                wo[3] = make_int4(ov[12], ov[13], ov[14], ov[15]);
                if (lane == 0) {
                    g_cnt[ex] = total;
                    out[CNT_OFF + ex] = (float)total;
                }
            }
        }

        pbar();

        // Phase 3: emit inverse map from register-held (e, rk).
        const int slot = e * MAX_TOK + g_wcount[e][chunk] + rk;
        g_src[slot] = a;

        pbar();   // all planners' g_src/g_cnt globally visible past this point

        // Release: each planner block sets 16 of the 1024 spread flags.
        if (threadIdx.x < 16)
            *(volatile unsigned*)&g_flag[b * 16 + threadIdx.x][0] = epoch + 1u;
        return;
    }

    // ---------------- Slot blocks (bid 64..32831) --------------------------
    const int k = b - PLANNERS;                        // slot id 0..32767
    const int row = k & (NSYNC - 1);
    if (threadIdx.x == 0) {
        // Spread ticket: this row gets exactly 32 increments per replay.
        const unsigned t = atomicAdd(&g_tick[row][0], 1u);
        const unsigned tgt = (t >> 5) + 1u;            // replay epoch + 1
        while (*(volatile unsigned*)&g_flag[row][0] < tgt) { }
        __threadfence();
    }
    __syncthreads();   // block-wide: data reads below happen after flag observed

    const int slot = k;
    const int e    = slot >> 10;
    const int si   = slot & (MAX_TOK - 1);
    const int t    = threadIdx.x;
    float4* dst = reinterpret_cast<float4*>(out + (size_t)slot * HIDDEN);
    float4* md  = reinterpret_cast<float4*>(out + META_OFF + (size_t)slot * META_LEN);

    if (si < g_cnt[e]) {
        const int a   = g_src[slot];
        const int c   = a >> 12;
        const int n   = a & (N_PER_CHIP - 1);
        const int tok = n >> 2;
        const float4* src =
            reinterpret_cast<const float4*>(x + ((size_t)c * SEQ + tok) * HIDDEN);
        float4 v0 = src[t];
        float4 v1 = src[t + 256];
        dst[t]       = v0;
        dst[t + 256] = v1;
        if (t == 0) {
            __nv_bfloat16 hb = __float2bfloat16(w[a]);
            unsigned short bits = __bfloat16_as_ushort(hb);
            md[0] = make_float4((float)c, (float)tok, (float)(n & 3), (float)e);
            md[1] = make_float4((float)bits, 0.f, 0.f, 0.f);
        }
    } else {
        const float4 z = make_float4(0.f, 0.f, 0.f, 0.f);
        dst[t]       = z;
        dst[t + 256] = z;
        if (t == 0) {
            const float4 neg = make_float4(-1.f, -1.f, -1.f, -1.f);
            md[0] = neg;
            md[1] = neg;
        }
    }
}

// ---------------------------------------------------------------------------
extern "C" void kernel_launch(void* const* d_in, const int* in_sizes, int n_in,
                              void* d_out, int out_size) {
    const float* x   = (const float*)d_in[0];   // [4,1024,2048] f32
    const float* wts = (const float*)d_in[1];   // [4,1024,4]    f32
    const int*   ind = (const int*)  d_in[2];   // [4,1024,4]    i32
    float* out = (float*)d_out;

    dispatch_kernel<<<PLANNERS + TOTAL_SLOTS, THREADS>>>(x, wts, ind, out);
}

// round 17
// speedup vs baseline: 1.2342x; 1.2342x over previous
#include <cuda_runtime.h>
#include <cuda_bf16.h>
#include <cstdint>

// Problem constants
#define NUM_CHIPS 4
#define SEQ 1024
#define HIDDEN 2048
#define TOP_K 4
#define N_EXPERTS 32
#define MAX_TOK 1024
#define META_LEN 8
#define N_PER_CHIP (SEQ * TOP_K)           // 4096
#define N_TOTAL (NUM_CHIPS * N_PER_CHIP)   // 16384 assignments
#define N_CHUNKS (N_TOTAL / 32)            // 512 warp-chunks, chip-major
#define TOTAL_SLOTS (N_EXPERTS * MAX_TOK)  // 32768
#define BUF_ELEMS ((size_t)TOTAL_SLOTS * HIDDEN)
#define META_OFF  BUF_ELEMS
#define CNT_OFF   (BUF_ELEMS + (size_t)TOTAL_SLOTS * META_LEN)

#define PLAN_BLOCKS 16          // blocks 0..15 plan 32 chunks each; block 16 emits totals

// Scratch (no allocations allowed)
__device__ int g_src[TOTAL_SLOTS];   // slot -> assignment id (first cnt_e per expert valid)
__device__ int g_cnt[N_EXPERTS];     // per-expert totals

// ---------------------------------------------------------------------------
// Planning: 17 blocks x 1024 threads, NO cross-block sync. Each block
// redundantly histograms the assignments preceding its region:
//   slot(a) = e*1024 + hist_before_block[e] + within_block_prefix[e] + rank
// Block 16 computes the full histogram -> g_cnt + output counters.
// Deep unroll: the straggler's serial L2 latency batches drop ~4x.
// ---------------------------------------------------------------------------
__global__ void __launch_bounds__(1024) plan_kernel(const int* __restrict__ idx,
                                                    float* __restrict__ out) {
    __shared__ int s_hist[N_EXPERTS];          // histogram of preceding region
    __shared__ int s_cnt[32][N_EXPERTS];       // per-warp per-expert counts (this block)
    __shared__ int s_pref[N_EXPERTS][32];      // exclusive warp prefix per expert

    const int warp = threadIdx.x >> 5;
    const int lane = threadIdx.x & 31;
    const unsigned lt = (1u << lane) - 1u;
    const int b = blockIdx.x;

    if (threadIdx.x < N_EXPERTS) s_hist[threadIdx.x] = 0;
    s_cnt[warp][lane] = 0;

    if (b == PLAN_BLOCKS) {
        // Totals block: histogram ALL 512 chunks.
        __syncthreads();
#pragma unroll 8
        for (int ch = warp; ch < N_CHUNKS; ch += 32) {
            const int e = __ldg(&idx[ch * 32 + lane]);
            const unsigned m = __match_any_sync(0xFFFFFFFFu, e);
            if ((m & lt) == 0) atomicAdd(&s_hist[e], __popc(m));
        }
        __syncthreads();
        if (threadIdx.x < N_EXPERTS) {
            g_cnt[threadIdx.x] = s_hist[threadIdx.x];
            out[CNT_OFF + threadIdx.x] = (float)s_hist[threadIdx.x];
        }
        __threadfence();
        cudaTriggerProgrammaticLaunchCompletion();
        return;
    }

    // Own chunk: rank + count (warp w owns chunk b*32+w).
    const int a = (b * 32 + warp) * 32 + lane;
    const int e = __ldg(&idx[a]);
    const unsigned m = __match_any_sync(0xFFFFFFFFu, e);
    const int rk = __popc(m & lt);
    __syncwarp();
    if (rk == 0) s_cnt[warp][e] = __popc(m);   // leaders hold distinct e: no conflict

    // Redundant histogram of preceding region [0, b*32) chunks (deep unroll -> MLP).
#pragma unroll 8
    for (int ch = warp; ch < b * 32; ch += 32) {
        const int pe = __ldg(&idx[ch * 32 + lane]);
        const unsigned pm = __match_any_sync(0xFFFFFFFFu, pe);
        if ((pm & lt) == 0) atomicAdd(&s_hist[pe], __popc(pm));
    }
    __syncthreads();

    // Warp ex scans expert ex's 32 per-warp counts (exclusive).
    {
        const int ex = warp;
        const int c = s_cnt[lane][ex];
        int s = c;
#pragma unroll
        for (int d = 1; d < 32; d <<= 1) {
            int t = __shfl_up_sync(0xFFFFFFFFu, s, d);
            if (lane >= d) s += t;
        }
        s_pref[ex][lane] = s - c;
    }
    __syncthreads();

    // Emit inverse map, then PDL trigger.
    const int slot = e * MAX_TOK + s_hist[e] + s_pref[e][warp] + rk;
    g_src[slot] = a;
    __threadfence();
    cudaTriggerProgrammaticLaunchCompletion();
}

// ---------------------------------------------------------------------------
// Gather: the proven champion shape — one block per slot, 256 threads, plain
// float4 loads/stores (measured 52.5-52.7us @ ~68% DRAM). PDL-gated entry.
// ---------------------------------------------------------------------------
__global__ void __launch_bounds__(256) gather_kernel(const float* __restrict__ x,
                                                     const float* __restrict__ w,
                                                     float* __restrict__ out) {
    cudaGridDependencySynchronize();

    const int slot = blockIdx.x;
    const int e    = slot >> 10;
    const int si   = slot & (MAX_TOK - 1);
    const int t    = threadIdx.x;
    float4* dst = reinterpret_cast<float4*>(out + (size_t)slot * HIDDEN);
    float4* md  = reinterpret_cast<float4*>(out + META_OFF + (size_t)slot * META_LEN);

    if (si < g_cnt[e]) {
        const int a   = g_src[slot];
        const int c   = a >> 12;
        const int n   = a & (N_PER_CHIP - 1);
        const int tok = n >> 2;
        const float4* src =
            reinterpret_cast<const float4*>(x + ((size_t)c * SEQ + tok) * HIDDEN);
        float4 v0 = src[t];
        float4 v1 = src[t + 256];
        dst[t]       = v0;
        dst[t + 256] = v1;
        if (t == 0) {
            __nv_bfloat16 hb = __float2bfloat16(w[a]);
            unsigned short bits = __bfloat16_as_ushort(hb);
            md[0] = make_float4((float)c, (float)tok, (float)(n & 3), (float)e);
            md[1] = make_float4((float)bits, 0.f, 0.f, 0.f);
        }
    } else {
        const float4 z = make_float4(0.f, 0.f, 0.f, 0.f);
        dst[t]       = z;
        dst[t + 256] = z;
        if (t == 0) {
            const float4 neg = make_float4(-1.f, -1.f, -1.f, -1.f);
            md[0] = neg;
            md[1] = neg;
        }
    }
}

// ---------------------------------------------------------------------------
extern "C" void kernel_launch(void* const* d_in, const int* in_sizes, int n_in,
                              void* d_out, int out_size) {
    const float* x   = (const float*)d_in[0];   // [4,1024,2048] f32
    const float* wts = (const float*)d_in[1];   // [4,1024,4]    f32
    const int*   ind = (const int*)  d_in[2];   // [4,1024,4]    i32
    float* out = (float*)d_out;

    plan_kernel<<<PLAN_BLOCKS + 1, 1024>>>(ind, out);

    // Gather with programmatic dependent launch: pre-spawn while plan drains.
    cudaLaunchAttribute attrs[1];
    attrs[0].id = cudaLaunchAttributeProgrammaticStreamSerialization;
    attrs[0].val.programmaticStreamSerializationAllowed = 1;

    cudaLaunchConfig_t cfg = {};
    cfg.gridDim  = dim3(TOTAL_SLOTS, 1, 1);
    cfg.blockDim = dim3(256, 1, 1);
    cfg.dynamicSmemBytes = 0;
    cfg.stream = 0;
    cfg.attrs = attrs;
    cfg.numAttrs = 1;

    cudaLaunchKernelEx(&cfg, gather_kernel, x, wts, out);
}